// round 4
// baseline (speedup 1.0000x reference)
#include <cuda_runtime.h>
#include <cuda_bf16.h>

#define MAXN 100000
#define MAXE 1600000
#define DD   64
#define SCAN_T 1024

// Scratch (device globals — allocations forbidden).
__device__ int   g_cnt[MAXN];        // in-degree (excluding self loop)
__device__ int   g_row[MAXN];        // CSR row start (exclusive prefix of cnt)
__device__ int   g_cur[MAXN];        // fill cursor
__device__ float g_dinv[MAXN];       // deg^-1/2 (deg includes self loop)
__device__ int   g_srcs[MAXE];       // CSR column (src) indices, grouped by dst
__device__ float g_agg[(size_t)MAXN * DD];  // aggregated rows (25.6 MB)

// K1: zero histogram
__global__ void k_zero(int n) {
    int i = blockIdx.x * blockDim.x + threadIdx.x;
    if (i < n) g_cnt[i] = 0;
}

// K2: histogram of dst
__global__ void k_count(const int* __restrict__ ei, int E) {
    int e = blockIdx.x * blockDim.x + threadIdx.x;
    if (e < E) atomicAdd(&g_cnt[ei[E + e]], 1);
}

// K3: exclusive prefix scan of g_cnt -> g_row, g_cur; also dinv = rsqrt(cnt+1).
// Single block, 1024 threads, chunked. n=100K -> ~98 elems/thread, ~few us.
__global__ void k_scan(int n) {
    __shared__ int ssum[SCAN_T];
    int t = threadIdx.x;
    int chunk = (n + SCAN_T - 1) / SCAN_T;
    int beg = t * chunk;
    int end = min(beg + chunk, n);
    int s = 0;
    for (int i = beg; i < end; i++) s += g_cnt[i];
    ssum[t] = s;
    __syncthreads();
    // Hillis-Steele inclusive scan in smem
    for (int d = 1; d < SCAN_T; d <<= 1) {
        int v = (t >= d) ? ssum[t - d] : 0;
        __syncthreads();
        ssum[t] += v;
        __syncthreads();
    }
    int off = ssum[t] - s;  // exclusive offset for this thread's chunk
    for (int i = beg; i < end; i++) {
        int c = g_cnt[i];
        g_row[i] = off;
        g_cur[i] = off;
        g_dinv[i] = rsqrtf((float)(c + 1));
        off += c;
    }
}

// K4: CSR fill — scatter src indices into per-dst buckets.
__global__ void k_fill(const int* __restrict__ ei, int E) {
    int e = blockIdx.x * blockDim.x + threadIdx.x;
    if (e >= E) return;
    int s = ei[e];
    int d = ei[E + e];
    int pos = atomicAdd(&g_cur[d], 1);
    g_srcs[pos] = s;
}

// K5: pull aggregation. 16 lanes per destination node; each lane owns one
// float4 chunk of the 64-wide row. No atomics; agg written once.
__global__ void k_pull(const float4* __restrict__ x4, int n) {
    int gid = blockIdx.x * blockDim.x + threadIdx.x;
    int node = gid >> 4;
    int lane = gid & 15;
    if (node >= n) return;

    float di = g_dinv[node];
    // self-loop contribution: dinv^2 * x[node]
    float4 acc = __ldg(&x4[(size_t)node * 16 + lane]);
    float s2 = di * di;
    acc.x *= s2; acc.y *= s2; acc.z *= s2; acc.w *= s2;

    int beg = g_row[node];
    int cnt = g_cnt[node];
    int j = 0;
    // unroll by 2 for MLP on the src->x4 dependent chain
    for (; j + 1 < cnt; j += 2) {
        int s0 = __ldg(&g_srcs[beg + j]);
        int s1 = __ldg(&g_srcs[beg + j + 1]);
        float n0 = di * __ldg(&g_dinv[s0]);
        float n1 = di * __ldg(&g_dinv[s1]);
        float4 v0 = __ldg(&x4[(size_t)s0 * 16 + lane]);
        float4 v1 = __ldg(&x4[(size_t)s1 * 16 + lane]);
        acc.x += n0 * v0.x + n1 * v1.x;
        acc.y += n0 * v0.y + n1 * v1.y;
        acc.z += n0 * v0.z + n1 * v1.z;
        acc.w += n0 * v0.w + n1 * v1.w;
    }
    if (j < cnt) {
        int s0 = __ldg(&g_srcs[beg + j]);
        float n0 = di * __ldg(&g_dinv[s0]);
        float4 v0 = __ldg(&x4[(size_t)s0 * 16 + lane]);
        acc.x += n0 * v0.x;
        acc.y += n0 * v0.y;
        acc.z += n0 * v0.z;
        acc.w += n0 * v0.w;
    }
    reinterpret_cast<float4*>(g_agg)[(size_t)node * 16 + lane] = acc;
}

// K6: out = agg @ W^T + b. One node per thread, W^T staged in smem.
__global__ void k_gemm(const float* __restrict__ W,
                       const float* __restrict__ b,
                       float* __restrict__ out, int n) {
    __shared__ float sW[DD * DD];  // transposed: sW[k][j] = W[j][k]
    for (int idx = threadIdx.x; idx < DD * DD; idx += blockDim.x) {
        int j = idx >> 6, k = idx & 63;
        sW[k * DD + j] = W[idx];
    }
    __syncthreads();

    int node = blockIdx.x * blockDim.x + threadIdx.x;
    if (node >= n) return;

    float4 acc[16];
    const float4* b4 = reinterpret_cast<const float4*>(b);
#pragma unroll
    for (int jj = 0; jj < 16; jj++) acc[jj] = __ldg(&b4[jj]);

    const float4* a4 = reinterpret_cast<const float4*>(g_agg) + (size_t)node * 16;
#pragma unroll
    for (int kk = 0; kk < 16; kk++) {
        float4 av = a4[kk];
#pragma unroll
        for (int s = 0; s < 4; s++) {
            float v = (s == 0) ? av.x : (s == 1) ? av.y : (s == 2) ? av.z : av.w;
            const float4* wr = reinterpret_cast<const float4*>(&sW[(kk * 4 + s) * DD]);
#pragma unroll
            for (int jj = 0; jj < 16; jj++) {
                float4 w = wr[jj];
                acc[jj].x += v * w.x;
                acc[jj].y += v * w.y;
                acc[jj].z += v * w.z;
                acc[jj].w += v * w.w;
            }
        }
    }

    float4* o4 = reinterpret_cast<float4*>(out) + (size_t)node * 16;
#pragma unroll
    for (int jj = 0; jj < 16; jj++) o4[jj] = acc[jj];
}

// ---------------------------------------------------------------------------
extern "C" void kernel_launch(void* const* d_in, const int* in_sizes, int n_in,
                              void* d_out, int out_size) {
    const float* x  = (const float*)d_in[0];
    const int*   ei = (const int*)d_in[1];
    const float* W  = (const float*)d_in[2];
    const float* b  = (const float*)d_in[3];
    float* out = (float*)d_out;

    int D = in_sizes[3];          // 64
    int n = in_sizes[0] / D;      // 100000
    int E = in_sizes[1] / 2;      // 1600000

    const int T = 256;
    k_zero <<<(n + T - 1) / T, T>>>(n);
    k_count<<<(E + T - 1) / T, T>>>(ei, E);
    k_scan <<<1, SCAN_T>>>(n);
    k_fill <<<(E + T - 1) / T, T>>>(ei, E);

    int pull_work = n * 16;
    k_pull <<<(pull_work + T - 1) / T, T>>>((const float4*)x, n);

    k_gemm <<<(n + T - 1) / T, T>>>(W, b, out, n);
}